// round 2
// baseline (speedup 1.0000x reference)
#include <cuda_runtime.h>
#include <math.h>

#define BATCH 512
#define SEQ   200
#define FIN   32
#define EMB   128
#define HID   128
#define GATE  512            // 4*HID
#define NL    2
#define MROWS (BATCH*SEQ)    // 102400

// ---------------- scratch (__device__ globals: no allocations allowed) ----------------
__device__ float  g_xs[(size_t)SEQ*BATCH*EMB];          // [t][b][e]      52 MB
__device__ float  g_A [(size_t)MROWS*NL*GATE];          // [t*512+b][1024] 419 MB
__device__ float  g_hs[(size_t)BATCH*SEQ*HID];          // [b][t][h]      52 MB
__device__ float  g_f1[(size_t)BATCH*SEQ*EMB];          // [b][t][e]      52 MB
__device__ float  g_Mb[(size_t)BATCH*SEQ*SEQ];          // [b][n][n']     82 MB
__device__ float4 g_Wt4[NL*(HID/4)*GATE];               // Whh transposed: [l][k4][j]
__device__ float  g_blstm[NL*GATE];                     // b_ih + b_hh

__device__ __forceinline__ float sigf(float x) { return 1.0f/(1.0f+expf(-x)); }

// ---------------- prep: transpose Whh to k-major float4, sum LSTM biases ----------------
__global__ void prep_kernel(const float* __restrict__ w_hh,
                            const float* __restrict__ b_ih,
                            const float* __restrict__ b_hh) {
    int idx = blockIdx.x*blockDim.x + threadIdx.x;
    int stride = gridDim.x*blockDim.x;
    const int tot = NL*(HID/4)*GATE;
    for (int q = idx; q < tot; q += stride) {
        int j  = q % GATE;
        int k4 = (q / GATE) % (HID/4);
        int l  = q / (GATE*(HID/4));
        const float* wr = w_hh + ((size_t)(l*GATE + j))*HID + k4*4;
        g_Wt4[q] = make_float4(wr[0], wr[1], wr[2], wr[3]);
    }
    for (int q = idx; q < NL*GATE; q += stride)
        g_blstm[q] = b_ih[q] + b_hh[q];
}

// ---------------- generic fp32 GEMM: C = act(A[M,K] @ B[N,K]^T + bias) ----------------
// 128x128 tile, full K (<=128) staged in smem row-major with XOR swizzle,
// 256 threads, 8x8 micro-tile per thread via float4 k-chunks.
// remap=1: row m=(b*SEQ+t) is written to output row (t*BATCH+b)  (for [t][b][e] layout)
__global__ __launch_bounds__(256) void gemm_kernel(
    const float* __restrict__ A, const float* __restrict__ B,
    const float* __restrict__ bias, float* __restrict__ C,
    int M, int N, int K, int act, int remap)
{
    extern __shared__ float4 sm4[];
    const int K4 = K >> 2;
    float4* As4 = sm4;
    float4* Bs4 = sm4 + 128*K4;

    const int m0 = blockIdx.y * 128;
    const int n0 = blockIdx.x * 128;
    const int tid = threadIdx.x;

    // load A tile (rows always valid: M % 128 == 0 for all uses)
    for (int q = tid; q < 128*K4; q += 256) {
        int row = q / K4, k4 = q % K4;
        float4 v = *(const float4*)(A + ((size_t)(m0+row))*K + (k4<<2));
        As4[row*K4 + (k4 ^ ((row>>3)&7))] = v;
    }
    // load B tile (guard N)
    for (int q = tid; q < 128*K4; q += 256) {
        int row = q / K4, k4 = q % K4;
        float4 v = make_float4(0.f,0.f,0.f,0.f);
        if (n0 + row < N)
            v = *(const float4*)(B + ((size_t)(n0+row))*K + (k4<<2));
        Bs4[row*K4 + (k4 ^ ((row>>3)&7))] = v;
    }
    __syncthreads();

    const int tx = tid & 15, ty = tid >> 4;
    const int swa = ty & 7, swb = tx & 7;

    float acc[8][8];
    #pragma unroll
    for (int i = 0; i < 8; i++)
        #pragma unroll
        for (int j = 0; j < 8; j++) acc[i][j] = 0.f;

    for (int k4 = 0; k4 < K4; k4++) {
        float4 av[8], bv[8];
        int ka = k4 ^ swa, kb = k4 ^ swb;
        #pragma unroll
        for (int ii = 0; ii < 8; ii++) av[ii] = As4[(ty*8+ii)*K4 + ka];
        #pragma unroll
        for (int jj = 0; jj < 8; jj++) bv[jj] = Bs4[(tx*8+jj)*K4 + kb];
        #pragma unroll
        for (int ii = 0; ii < 8; ii++)
            #pragma unroll
            for (int jj = 0; jj < 8; jj++) {
                float a = acc[ii][jj];
                a = fmaf(av[ii].x, bv[jj].x, a);
                a = fmaf(av[ii].y, bv[jj].y, a);
                a = fmaf(av[ii].z, bv[jj].z, a);
                a = fmaf(av[ii].w, bv[jj].w, a);
                acc[ii][jj] = a;
            }
    }

    #pragma unroll
    for (int ii = 0; ii < 8; ii++) {
        int m = m0 + ty*8 + ii;
        size_t orow;
        if (remap) { int b = m / SEQ; int t = m - b*SEQ; orow = (size_t)t*BATCH + b; }
        else       { orow = (size_t)m; }
        #pragma unroll
        for (int jj = 0; jj < 8; jj++) {
            int n = n0 + tx*8 + jj;
            if (n < N) {
                float v = acc[ii][jj] + bias[n];
                if (act) v = (v >= 0.f) ? v : 0.01f*v;
                C[orow*(size_t)N + n] = v;
            }
        }
    }
}

// ---------------- LSTM recurrence: 128 CTAs x 4 batch elems, no global sync ----------------
// Each thread j (512 threads) computes gate row j for its 4 batch elements.
// Whh (k-major float4): first KC=24 k4-rows cached in 192KB smem, rest from L2.
#define KC 24
__global__ __launch_bounds__(512) void lstm_kernel(const float* __restrict__ A,
                                                   float* __restrict__ hs_out)
{
    __shared__ float4 h4[4][HID/4];     // h state, float4 over k
    __shared__ float  c_s[4][HID];
    __shared__ float  g_s[4][GATE];
    extern __shared__ float4 Wc[];      // KC*GATE float4 = 192KB

    const int j  = threadIdx.x;
    const int bb = blockIdx.x * 4;

    if (j < 128) { int b = j >> 5, k4 = j & 31; h4[b][k4] = make_float4(0.f,0.f,0.f,0.f); }
    { int b = j >> 7, hh = j & 127; c_s[b][hh] = 0.f; }

    for (int l = 0; l < NL; l++) {
        const float4* W = g_Wt4 + l*(HID/4)*GATE;
        const float bias = g_blstm[l*GATE + j];
        __syncthreads();
        for (int q = j; q < KC*GATE; q += 512) Wc[q] = W[q];
        __syncthreads();

        for (int t = 0; t < SEQ; t++) {
            const float* Ar = A + ((size_t)(t*BATCH + bb))*(NL*GATE) + l*GATE + j;
            float a0 = Ar[0];
            float a1 = Ar[NL*GATE];
            float a2 = Ar[2*NL*GATE];
            float a3 = Ar[3*NL*GATE];

            float s0=0.f, s1=0.f, s2=0.f, s3=0.f;
            #pragma unroll 8
            for (int k4 = 0; k4 < KC; k4++) {
                float4 w  = Wc[k4*GATE + j];
                float4 x0 = h4[0][k4], x1 = h4[1][k4], x2 = h4[2][k4], x3 = h4[3][k4];
                s0 = fmaf(w.x,x0.x, fmaf(w.y,x0.y, fmaf(w.z,x0.z, fmaf(w.w,x0.w, s0))));
                s1 = fmaf(w.x,x1.x, fmaf(w.y,x1.y, fmaf(w.z,x1.z, fmaf(w.w,x1.w, s1))));
                s2 = fmaf(w.x,x2.x, fmaf(w.y,x2.y, fmaf(w.z,x2.z, fmaf(w.w,x2.w, s2))));
                s3 = fmaf(w.x,x3.x, fmaf(w.y,x3.y, fmaf(w.z,x3.z, fmaf(w.w,x3.w, s3))));
            }
            #pragma unroll
            for (int k4 = KC; k4 < HID/4; k4++) {
                float4 w  = W[k4*GATE + j];
                float4 x0 = h4[0][k4], x1 = h4[1][k4], x2 = h4[2][k4], x3 = h4[3][k4];
                s0 = fmaf(w.x,x0.x, fmaf(w.y,x0.y, fmaf(w.z,x0.z, fmaf(w.w,x0.w, s0))));
                s1 = fmaf(w.x,x1.x, fmaf(w.y,x1.y, fmaf(w.z,x1.z, fmaf(w.w,x1.w, s1))));
                s2 = fmaf(w.x,x2.x, fmaf(w.y,x2.y, fmaf(w.z,x2.z, fmaf(w.w,x2.w, s2))));
                s3 = fmaf(w.x,x3.x, fmaf(w.y,x3.y, fmaf(w.z,x3.z, fmaf(w.w,x3.w, s3))));
            }
            g_s[0][j] = s0 + a0 + bias;
            g_s[1][j] = s1 + a1 + bias;
            g_s[2][j] = s2 + a2 + bias;
            g_s[3][j] = s3 + a3 + bias;
            __syncthreads();

            if (j < HID) {
                #pragma unroll
                for (int b = 0; b < 4; b++) {
                    float ig = g_s[b][j];
                    float fg = g_s[b][HID   + j];
                    float gg = g_s[b][2*HID + j];
                    float og = g_s[b][3*HID + j];
                    float cc = sigf(fg)*c_s[b][j] + sigf(ig)*tanhf(gg);
                    float hh = sigf(og)*tanhf(cc);
                    c_s[b][j] = cc;
                    ((float*)h4)[b*HID + j] = hh;
                    if (l == NL-1)
                        hs_out[((size_t)(bb+b)*SEQ + t)*HID + j] = hh;
                }
            }
            __syncthreads();
        }
    }
}

// ---------------- fused sinkhorn: one CTA per batch elem, 160KB matrix in smem ----------------
__global__ __launch_bounds__(256) void sinkhorn_kernel(const float* __restrict__ Min,
                                                       float* __restrict__ out)
{
    extern __shared__ float Ms[];   // SEQ*SEQ floats
    const int b = blockIdx.x, tid = threadIdx.x;
    const float4* src = (const float4*)(Min + (size_t)b*SEQ*SEQ);
    float4* dst = (float4*)(out + (size_t)b*SEQ*SEQ);

    for (int q = tid; q < SEQ*SEQ/4; q += 256) {
        float4 v = src[q];
        v.x = expf(v.x); v.y = expf(v.y); v.z = expf(v.z); v.w = expf(v.w);
        ((float4*)Ms)[q] = v;
    }
    __syncthreads();

    const int lane = tid & 31, w = tid >> 5;   // 8 warps
    for (int it = 0; it < 5; it++) {
        // row normalize (sum over last dim, contiguous)
        for (int r = w; r < SEQ; r += 8) {
            float s = 0.f;
            for (int q = lane; q < SEQ; q += 32) s += Ms[r*SEQ + q];
            #pragma unroll
            for (int off = 16; off; off >>= 1) s += __shfl_xor_sync(0xffffffffu, s, off);
            float inv = 1.0f / s;
            for (int q = lane; q < SEQ; q += 32) Ms[r*SEQ + q] *= inv;
        }
        __syncthreads();
        // column normalize (sum over middle dim, stride SEQ)
        if (tid < SEQ) {
            float s = 0.f;
            for (int r = 0; r < SEQ; r++) s += Ms[r*SEQ + tid];
            float inv = 1.0f / s;
            for (int r = 0; r < SEQ; r++) Ms[r*SEQ + tid] *= inv;
        }
        __syncthreads();
    }

    for (int q = tid; q < SEQ*SEQ/4; q += 256) dst[q] = ((const float4*)Ms)[q];
}

// ---------------- launch ----------------
extern "C" void kernel_launch(void* const* d_in, const int* in_sizes, int n_in,
                              void* d_out, int out_size)
{
    const float* x     = (const float*)d_in[0];
    const float* w_emb = (const float*)d_in[1];
    const float* b_emb = (const float*)d_in[2];
    const float* w_ih  = (const float*)d_in[3];
    const float* w_hh  = (const float*)d_in[4];
    const float* b_ih  = (const float*)d_in[5];
    const float* b_hh  = (const float*)d_in[6];
    const float* w_fc1 = (const float*)d_in[7];
    const float* b_fc1 = (const float*)d_in[8];
    const float* w_fc2 = (const float*)d_in[9];
    const float* b_fc2 = (const float*)d_in[10];
    float* out = (float*)d_out;

    float *xs, *Ab, *hs, *f1, *Mb, *blstm;
    cudaGetSymbolAddress((void**)&xs,    g_xs);
    cudaGetSymbolAddress((void**)&Ab,    g_A);
    cudaGetSymbolAddress((void**)&hs,    g_hs);
    cudaGetSymbolAddress((void**)&f1,    g_f1);
    cudaGetSymbolAddress((void**)&Mb,    g_Mb);
    cudaGetSymbolAddress((void**)&blstm, g_blstm);

    cudaFuncSetAttribute(gemm_kernel,     cudaFuncAttributeMaxDynamicSharedMemorySize, 131072);
    cudaFuncSetAttribute(lstm_kernel,     cudaFuncAttributeMaxDynamicSharedMemorySize, KC*GATE*16);
    cudaFuncSetAttribute(sinkhorn_kernel, cudaFuncAttributeMaxDynamicSharedMemorySize, SEQ*SEQ*4);

    // 1) Whh transpose + bias sum
    prep_kernel<<<64, 256>>>(w_hh, b_ih, b_hh);
    // 2) embedding: e = leaky(x @ w_emb^T + b_emb), stored [t][b][e]
    gemm_kernel<<<dim3(1, MROWS/128), 256, 2*128*FIN*4>>>(x, w_emb, b_emb, xs,
                                                          MROWS, EMB, FIN, 1, 1);
    // 3) LSTM input projections for BOTH layers (same xs): A = xs @ Wih^T + (b_ih+b_hh)
    gemm_kernel<<<dim3(NL*GATE/128, MROWS/128), 256, 2*128*EMB*4>>>(xs, w_ih, blstm, Ab,
                                                          MROWS, NL*GATE, EMB, 0, 0);
    // 4) recurrence (both layers, batch-parallel)
    lstm_kernel<<<BATCH/4, 512, KC*GATE*16>>>(Ab, hs);
    // 5) fc1 with leaky
    gemm_kernel<<<dim3(1, MROWS/128), 256, 2*128*HID*4>>>(hs, w_fc1, b_fc1, f1,
                                                          MROWS, EMB, HID, 1, 0);
    // 6) fc2 -> M [b][n][n']
    gemm_kernel<<<dim3(2, MROWS/128), 256, 2*128*EMB*4>>>(f1, w_fc2, b_fc2, Mb,
                                                          MROWS, SEQ, EMB, 0, 0);
    // 7) sinkhorn (exp + 5x row/col normalize) fused in smem
    sinkhorn_kernel<<<BATCH, 256, SEQ*SEQ*4>>>(Mb, out);
}

// round 3
// speedup vs baseline: 1.2698x; 1.2698x over previous
#include <cuda_runtime.h>
#include <math.h>

#define BATCH 512
#define SEQ   200
#define FIN   32
#define EMB   128
#define HID   128
#define GATE  512            // 4*HID
#define NL    2
#define MROWS (BATCH*SEQ)    // 102400

// ---------------- scratch (__device__ globals: no allocations allowed) ----------------
__device__ float  g_xs[(size_t)SEQ*BATCH*EMB];          // [t][b][e]
__device__ float  g_A [(size_t)MROWS*NL*GATE];          // [t*512+b][1024]
__device__ float  g_hs[(size_t)BATCH*SEQ*HID];          // [b][t][h]
__device__ float  g_f1[(size_t)BATCH*SEQ*EMB];          // [b][t][e]
__device__ float  g_Mb[(size_t)BATCH*SEQ*SEQ];          // [b][n][n']
__device__ float4 g_Wt4[NL*(HID/4)*GATE];               // Whh transposed: [l][k4][j]
__device__ float  g_blstm[NL*GATE];                     // b_ih + b_hh

__device__ __forceinline__ float sigf(float x) { return 1.0f/(1.0f+expf(-x)); }

// packed fp32x2 FMA: d = a*b + d (elementwise on 2 packed fp32)
union f4u { float4 f4; unsigned long long u[2]; };

__device__ __forceinline__ void ffma2(unsigned long long& d,
                                      unsigned long long a,
                                      unsigned long long b) {
    asm("fma.rn.f32x2 %0, %1, %2, %0;" : "+l"(d) : "l"(a), "l"(b));
}
__device__ __forceinline__ float hadd2(unsigned long long v) {
    union { unsigned long long u; float2 f; } c; c.u = v;
    return c.f.x + c.f.y;
}

// ---------------- prep: transpose Whh to k-major float4, sum LSTM biases ----------------
__global__ void prep_kernel(const float* __restrict__ w_hh,
                            const float* __restrict__ b_ih,
                            const float* __restrict__ b_hh) {
    int idx = blockIdx.x*blockDim.x + threadIdx.x;
    int stride = gridDim.x*blockDim.x;
    const int tot = NL*(HID/4)*GATE;
    for (int q = idx; q < tot; q += stride) {
        int j  = q % GATE;
        int k4 = (q / GATE) % (HID/4);
        int l  = q / (GATE*(HID/4));
        const float* wr = w_hh + ((size_t)(l*GATE + j))*HID + k4*4;
        g_Wt4[q] = make_float4(wr[0], wr[1], wr[2], wr[3]);
    }
    for (int q = idx; q < NL*GATE; q += stride)
        g_blstm[q] = b_ih[q] + b_hh[q];
}

// ---------------- fp32 GEMM with packed f32x2 FMA: C = act(A[M,K] @ B[N,K]^T + bias) ----
// 128x128 tile, K<=128 staged in smem, 256 threads, 8x8 micro-tile.
// k-pairing: each float4 over k = two packed f32x2 operands; horizontal add at epilogue.
__global__ __launch_bounds__(256) void gemm_kernel(
    const float* __restrict__ A, const float* __restrict__ B,
    const float* __restrict__ bias, float* __restrict__ C,
    int M, int N, int K, int act, int remap)
{
    extern __shared__ float4 sm4[];
    const int K4 = K >> 2;
    float4* As4 = sm4;
    float4* Bs4 = sm4 + 128*K4;

    const int m0 = blockIdx.y * 128;
    const int n0 = blockIdx.x * 128;
    const int tid = threadIdx.x;

    for (int q = tid; q < 128*K4; q += 256) {
        int row = q / K4, k4 = q % K4;
        float4 v = *(const float4*)(A + ((size_t)(m0+row))*K + (k4<<2));
        As4[row*K4 + (k4 ^ ((row>>3)&7))] = v;
    }
    for (int q = tid; q < 128*K4; q += 256) {
        int row = q / K4, k4 = q % K4;
        float4 v = make_float4(0.f,0.f,0.f,0.f);
        if (n0 + row < N)
            v = *(const float4*)(B + ((size_t)(n0+row))*K + (k4<<2));
        Bs4[row*K4 + (k4 ^ ((row>>3)&7))] = v;
    }
    __syncthreads();

    const int tx = tid & 15, ty = tid >> 4;
    const int swa = ty & 7, swb = tx & 7;

    unsigned long long acc[8][8];
    #pragma unroll
    for (int i = 0; i < 8; i++)
        #pragma unroll
        for (int j = 0; j < 8; j++) acc[i][j] = 0ULL;

    for (int k4 = 0; k4 < K4; k4++) {
        int ka = k4 ^ swa, kb = k4 ^ swb;
        f4u av[8];
        #pragma unroll
        for (int ii = 0; ii < 8; ii++) av[ii].f4 = As4[(ty*8+ii)*K4 + ka];
        #pragma unroll
        for (int jj = 0; jj < 8; jj++) {
            f4u bv; bv.f4 = Bs4[(tx*8+jj)*K4 + kb];
            #pragma unroll
            for (int ii = 0; ii < 8; ii++) {
                ffma2(acc[ii][jj], av[ii].u[0], bv.u[0]);
                ffma2(acc[ii][jj], av[ii].u[1], bv.u[1]);
            }
        }
    }

    #pragma unroll
    for (int ii = 0; ii < 8; ii++) {
        int m = m0 + ty*8 + ii;
        size_t orow;
        if (remap) { int b = m / SEQ; int t = m - b*SEQ; orow = (size_t)t*BATCH + b; }
        else       { orow = (size_t)m; }
        #pragma unroll
        for (int jj = 0; jj < 8; jj++) {
            int n = n0 + tx*8 + jj;
            if (n < N) {
                float v = hadd2(acc[ii][jj]) + bias[n];
                if (act) v = (v >= 0.f) ? v : 0.01f*v;
                C[orow*(size_t)N + n] = v;
            }
        }
    }
}

// ---------------- LSTM recurrence: 128 CTAs x 4 batch, no global loads in steady state --
// Thread j computes gate row j for 4 batch elems. Whh split: KC k4-rows in smem,
// (32-KC) k4-rows in per-thread registers (weights are time-invariant!).
// Dot products via packed f32x2 (k-pairing).
#define KC 20
__global__ __launch_bounds__(512) void lstm_kernel(const float* __restrict__ A,
                                                   float* __restrict__ hs_out)
{
    __shared__ float h_s[4][HID];     // [b][k], k-contiguous (float4-readable)
    __shared__ float c_s[4][HID];
    __shared__ float g_s[4][GATE];
    extern __shared__ float4 Wc[];    // KC*GATE float4

    const int j  = threadIdx.x;
    const int bb = blockIdx.x * 4;
    const int ub = j >> 7, uh = j & 127;   // update-phase mapping: (batch, hid)

    h_s[ub][uh] = 0.f;
    c_s[ub][uh] = 0.f;

    for (int l = 0; l < NL; l++) {
        const float4* W = g_Wt4 + l*(HID/4)*GATE;
        const float bias = g_blstm[l*GATE + j];
        __syncthreads();
        for (int q = j; q < KC*GATE; q += 512) Wc[q] = W[q];
        f4u wr[32-KC];
        #pragma unroll
        for (int r = 0; r < 32-KC; r++) wr[r].f4 = W[(KC+r)*GATE + j];
        __syncthreads();

        for (int t = 0; t < SEQ; t++) {
            const float* Ar = A + ((size_t)(t*BATCH + bb))*(NL*GATE) + l*GATE + j;
            float a0 = Ar[0];
            float a1 = Ar[NL*GATE];
            float a2 = Ar[2*NL*GATE];
            float a3 = Ar[3*NL*GATE];

            unsigned long long s0=0ULL, s1=0ULL, s2=0ULL, s3=0ULL;
            #pragma unroll
            for (int k4 = 0; k4 < KC; k4++) {
                f4u wv; wv.f4 = Wc[k4*GATE + j];
                f4u h0; h0.f4 = *(const float4*)&h_s[0][k4<<2];
                f4u h1; h1.f4 = *(const float4*)&h_s[1][k4<<2];
                f4u h2; h2.f4 = *(const float4*)&h_s[2][k4<<2];
                f4u h3; h3.f4 = *(const float4*)&h_s[3][k4<<2];
                ffma2(s0, wv.u[0], h0.u[0]); ffma2(s0, wv.u[1], h0.u[1]);
                ffma2(s1, wv.u[0], h1.u[0]); ffma2(s1, wv.u[1], h1.u[1]);
                ffma2(s2, wv.u[0], h2.u[0]); ffma2(s2, wv.u[1], h2.u[1]);
                ffma2(s3, wv.u[0], h3.u[0]); ffma2(s3, wv.u[1], h3.u[1]);
            }
            #pragma unroll
            for (int r = 0; r < 32-KC; r++) {
                int k4 = KC + r;
                f4u h0; h0.f4 = *(const float4*)&h_s[0][k4<<2];
                f4u h1; h1.f4 = *(const float4*)&h_s[1][k4<<2];
                f4u h2; h2.f4 = *(const float4*)&h_s[2][k4<<2];
                f4u h3; h3.f4 = *(const float4*)&h_s[3][k4<<2];
                ffma2(s0, wr[r].u[0], h0.u[0]); ffma2(s0, wr[r].u[1], h0.u[1]);
                ffma2(s1, wr[r].u[0], h1.u[0]); ffma2(s1, wr[r].u[1], h1.u[1]);
                ffma2(s2, wr[r].u[0], h2.u[0]); ffma2(s2, wr[r].u[1], h2.u[1]);
                ffma2(s3, wr[r].u[0], h3.u[0]); ffma2(s3, wr[r].u[1], h3.u[1]);
            }
            g_s[0][j] = hadd2(s0) + a0 + bias;
            g_s[1][j] = hadd2(s1) + a1 + bias;
            g_s[2][j] = hadd2(s2) + a2 + bias;
            g_s[3][j] = hadd2(s3) + a3 + bias;
            __syncthreads();

            // pointwise gate update: all 512 threads, one (b, h) pair each
            {
                float ig = g_s[ub][uh];
                float fg = g_s[ub][HID   + uh];
                float gg = g_s[ub][2*HID + uh];
                float og = g_s[ub][3*HID + uh];
                float cc = sigf(fg)*c_s[ub][uh] + sigf(ig)*tanhf(gg);
                float hh = sigf(og)*tanhf(cc);
                c_s[ub][uh] = cc;
                h_s[ub][uh] = hh;
                if (l == NL-1)
                    hs_out[((size_t)(bb+ub)*SEQ + t)*HID + uh] = hh;
            }
            __syncthreads();
        }
    }
}

// ---------------- fused sinkhorn: one CTA per batch elem, 160KB matrix in smem ----------
__global__ __launch_bounds__(256) void sinkhorn_kernel(const float* __restrict__ Min,
                                                       float* __restrict__ out)
{
    extern __shared__ float Ms[];   // SEQ*SEQ floats
    const int b = blockIdx.x, tid = threadIdx.x;
    const float4* src = (const float4*)(Min + (size_t)b*SEQ*SEQ);
    float4* dst = (float4*)(out + (size_t)b*SEQ*SEQ);

    for (int q = tid; q < SEQ*SEQ/4; q += 256) {
        float4 v = src[q];
        v.x = __expf(v.x); v.y = __expf(v.y); v.z = __expf(v.z); v.w = __expf(v.w);
        ((float4*)Ms)[q] = v;
    }
    __syncthreads();

    const int lane = tid & 31, w = tid >> 5;   // 8 warps
    for (int it = 0; it < 5; it++) {
        // row normalize (contiguous)
        for (int r = w; r < SEQ; r += 8) {
            float s = 0.f;
            for (int q = lane; q < SEQ; q += 32) s += Ms[r*SEQ + q];
            #pragma unroll
            for (int off = 16; off; off >>= 1) s += __shfl_xor_sync(0xffffffffu, s, off);
            float inv = 1.0f / s;
            for (int q = lane; q < SEQ; q += 32) Ms[r*SEQ + q] *= inv;
        }
        __syncthreads();
        // column normalize (stride SEQ, lanes conflict-free)
        if (tid < SEQ) {
            float s = 0.f;
            for (int r = 0; r < SEQ; r++) s += Ms[r*SEQ + tid];
            float inv = 1.0f / s;
            for (int r = 0; r < SEQ; r++) Ms[r*SEQ + tid] *= inv;
        }
        __syncthreads();
    }

    for (int q = tid; q < SEQ*SEQ/4; q += 256) dst[q] = ((const float4*)Ms)[q];
}

// ---------------- launch ----------------
extern "C" void kernel_launch(void* const* d_in, const int* in_sizes, int n_in,
                              void* d_out, int out_size)
{
    const float* x     = (const float*)d_in[0];
    const float* w_emb = (const float*)d_in[1];
    const float* b_emb = (const float*)d_in[2];
    const float* w_ih  = (const float*)d_in[3];
    const float* w_hh  = (const float*)d_in[4];
    const float* b_ih  = (const float*)d_in[5];
    const float* b_hh  = (const float*)d_in[6];
    const float* w_fc1 = (const float*)d_in[7];
    const float* b_fc1 = (const float*)d_in[8];
    const float* w_fc2 = (const float*)d_in[9];
    const float* b_fc2 = (const float*)d_in[10];
    float* out = (float*)d_out;

    float *xs, *Ab, *hs, *f1, *Mb, *blstm;
    cudaGetSymbolAddress((void**)&xs,    g_xs);
    cudaGetSymbolAddress((void**)&Ab,    g_A);
    cudaGetSymbolAddress((void**)&hs,    g_hs);
    cudaGetSymbolAddress((void**)&f1,    g_f1);
    cudaGetSymbolAddress((void**)&Mb,    g_Mb);
    cudaGetSymbolAddress((void**)&blstm, g_blstm);

    cudaFuncSetAttribute(gemm_kernel,     cudaFuncAttributeMaxDynamicSharedMemorySize, 131072);
    cudaFuncSetAttribute(lstm_kernel,     cudaFuncAttributeMaxDynamicSharedMemorySize, KC*GATE*16);
    cudaFuncSetAttribute(sinkhorn_kernel, cudaFuncAttributeMaxDynamicSharedMemorySize, SEQ*SEQ*4);

    // 1) Whh transpose + bias sum
    prep_kernel<<<64, 256>>>(w_hh, b_ih, b_hh);
    // 2) embedding: e = leaky(x @ w_emb^T + b_emb), stored [t][b][e]
    gemm_kernel<<<dim3(1, MROWS/128), 256, 2*128*(FIN/4)*16>>>(x, w_emb, b_emb, xs,
                                                          MROWS, EMB, FIN, 1, 1);
    // 3) LSTM input projections for BOTH layers: A = xs @ Wih^T + (b_ih+b_hh)
    gemm_kernel<<<dim3(NL*GATE/128, MROWS/128), 256, 2*128*(EMB/4)*16>>>(xs, w_ih, blstm, Ab,
                                                          MROWS, NL*GATE, EMB, 0, 0);
    // 4) recurrence (both layers, batch-parallel)
    lstm_kernel<<<BATCH/4, 512, KC*GATE*16>>>(Ab, hs);
    // 5) fc1 with leaky
    gemm_kernel<<<dim3(1, MROWS/128), 256, 2*128*(HID/4)*16>>>(hs, w_fc1, b_fc1, f1,
                                                          MROWS, EMB, HID, 1, 0);
    // 6) fc2 -> M [b][n][n']
    gemm_kernel<<<dim3(2, MROWS/128), 256, 2*128*(EMB/4)*16>>>(f1, w_fc2, b_fc2, Mb,
                                                          MROWS, SEQ, EMB, 0, 0);
    // 7) sinkhorn (exp + 5x row/col normalize) fused in smem
    sinkhorn_kernel<<<BATCH, 256, SEQ*SEQ*4>>>(Mb, out);
}

// round 5
// speedup vs baseline: 1.3464x; 1.0604x over previous
#include <cuda_runtime.h>
#include <cuda_bf16.h>
#include <mma.h>
#include <math.h>
#include <stdint.h>

#define BATCH 512
#define SEQ   200
#define FIN   32
#define EMB   128
#define HID   128
#define GATE  512            // 4*HID
#define NL    2
#define MROWS (BATCH*SEQ)    // 102400
#define KDIM  128

#if defined(__CUDA_ARCH__) && defined(__CUDA_ARCH_FEAT_SM103_ALL)
#define USE_TCGEN05 1
#else
#define USE_TCGEN05 0
#endif

// ---------------- scratch (__device__ globals) ----------------
__device__ float  g_A [(size_t)MROWS*NL*GATE];          // LSTM input projections (fp32)
__device__ float  g_Mb[(size_t)MROWS*SEQ];              // fc2 out [b][n][n']
__device__ float4 g_Wt4[NL*(HID/4)*GATE];               // Whh transposed k-major
__device__ float  g_blstm[NL*GATE];                     // b_ih + b_hh
__device__ float  g_zero[NL*GATE];                      // zero bias for gemm3

// bf16 hi/lo split operands for tensor GEMMs
__device__ __nv_bfloat16 g_xsh[(size_t)MROWS*EMB], g_xsl[(size_t)MROWS*EMB];
__device__ __nv_bfloat16 g_wihh[NL*GATE*EMB],      g_wihl[NL*GATE*EMB];
__device__ __nv_bfloat16 g_wf1h[EMB*HID],          g_wf1l[EMB*HID];
__device__ __nv_bfloat16 g_wf2h[SEQ*EMB],          g_wf2l[SEQ*EMB];
__device__ __nv_bfloat16 g_hsh[(size_t)MROWS*HID], g_hsl[(size_t)MROWS*HID];
__device__ __nv_bfloat16 g_f1h[(size_t)MROWS*EMB], g_f1l[(size_t)MROWS*EMB];

__device__ __forceinline__ void split2(float v, __nv_bfloat16& h, __nv_bfloat16& l) {
    h = __float2bfloat16(v);
    l = __float2bfloat16(v - __bfloat162float(h));
}

// packed fp32x2 FMA (embed + lstm scalar paths)
union f4u { float4 f4; unsigned long long u[2]; };
__device__ __forceinline__ void ffma2(unsigned long long& d,
                                      unsigned long long a,
                                      unsigned long long b) {
    asm("fma.rn.f32x2 %0, %1, %2, %0;" : "+l"(d) : "l"(a), "l"(b));
}
__device__ __forceinline__ float hadd2(unsigned long long v) {
    union { unsigned long long u; float2 f; } c; c.u = v;
    return c.f.x + c.f.y;
}

// fast activations (MUFU-based; error ~1e-7 rel, negligible vs 1e-3 gate)
__device__ __forceinline__ float fsig(float x)  { return __fdividef(1.f, 1.f + __expf(-x)); }
__device__ __forceinline__ float ftanh(float x) { return __fdividef(2.f, 1.f + __expf(-2.f*x)) - 1.f; }

// ---------------- tcgen05 helpers (only compiled for arch-specific 103a pass) ----------
#if USE_TCGEN05
__device__ __forceinline__ uint32_t smem_u32(const void* p) {
    uint32_t a;
    asm("{ .reg .u64 t; cvta.to.shared.u64 t, %1; cvt.u32.u64 %0, t; }" : "=r"(a) : "l"(p));
    return a;
}
#define TC_ALLOC(dst, n) \
    asm volatile("tcgen05.alloc.cta_group::1.sync.aligned.shared::cta.b32 [%0], %1;" \
                 :: "r"(dst), "r"((uint32_t)(n)) : "memory")
#define TC_RELINQ() \
    asm volatile("tcgen05.relinquish_alloc_permit.cta_group::1.sync.aligned;")
#define TC_DEALLOC(t, n) \
    asm volatile("tcgen05.dealloc.cta_group::1.sync.aligned.b32 %0, %1;" :: "r"(t), "r"((uint32_t)(n)))
#define TC_COMMIT(mbar) \
    asm volatile("tcgen05.commit.cta_group::1.mbarrier::arrive::one.shared::cluster.b64 [%0];" \
                 :: "r"(mbar) : "memory")
#define TC_FENCE_AFTER()  asm volatile("tcgen05.fence::after_thread_sync;" ::: "memory")
#define TC_WAIT_LD()      asm volatile("tcgen05.wait::ld.sync.aligned;" ::: "memory")
#define FENCE_ASYNC()     asm volatile("fence.proxy.async.shared::cta;" ::: "memory")
#define MBAR_INIT(a, c) \
    asm volatile("mbarrier.init.shared.b64 [%0], %1;" :: "r"(a), "r"((uint32_t)(c)) : "memory")
#define MBAR_WAIT(a, ph) do { \
    uint32_t _m = (a), _p = (ph); \
    asm volatile("{\n\t.reg .pred P1;\n\t" \
        "WL_%=:\n\t" \
        "mbarrier.try_wait.parity.acquire.cta.shared::cta.b64 P1, [%0], %1, 0x989680;\n\t" \
        "@P1 bra.uni WD_%=;\n\t" \
        "bra.uni WL_%=;\n\t" \
        "WD_%=:\n\t}" :: "r"(_m), "r"(_p) : "memory"); \
} while (0)
#define TC_LD_X32(r, addr) \
    asm volatile("tcgen05.ld.sync.aligned.32x32b.x32.b32 " \
        "{%0, %1, %2, %3, %4, %5, %6, %7, %8, %9, %10, %11, %12, %13, %14, %15, " \
        " %16, %17, %18, %19, %20, %21, %22, %23, %24, %25, %26, %27, %28, %29, %30, %31}, [%32];" \
        : "=r"((r)[0]),  "=r"((r)[1]),  "=r"((r)[2]),  "=r"((r)[3]), \
          "=r"((r)[4]),  "=r"((r)[5]),  "=r"((r)[6]),  "=r"((r)[7]), \
          "=r"((r)[8]),  "=r"((r)[9]),  "=r"((r)[10]), "=r"((r)[11]), \
          "=r"((r)[12]), "=r"((r)[13]), "=r"((r)[14]), "=r"((r)[15]), \
          "=r"((r)[16]), "=r"((r)[17]), "=r"((r)[18]), "=r"((r)[19]), \
          "=r"((r)[20]), "=r"((r)[21]), "=r"((r)[22]), "=r"((r)[23]), \
          "=r"((r)[24]), "=r"((r)[25]), "=r"((r)[26]), "=r"((r)[27]), \
          "=r"((r)[28]), "=r"((r)[29]), "=r"((r)[30]), "=r"((r)[31]) \
        : "r"(addr))

__device__ __forceinline__ uint64_t mk_desc(uint32_t addr) {
    const uint64_t base = (uint64_t(2) << 61) | (uint64_t(1) << 46)
                        | (uint64_t(64) << 32) | (uint64_t(1) << 16);
    return base | ((uint64_t)(addr >> 4) & 0x3FFF);
}
#define IDESC 0x8200490u   // fp32 acc, bf16 A/B, M=128, N=128

__device__ __forceinline__ void mma_f16_ss(uint32_t d, uint64_t ad, uint64_t bd, uint32_t en) {
    asm volatile("{\n\t.reg .pred p;\n\tsetp.ne.u32 p, %5, 0;\n\t"
        "tcgen05.mma.cta_group::1.kind::f16 [%0], %1, %2, %3, {%4,%4,%4,%4}, p;\n\t}"
        :: "r"(d), "l"(ad), "l"(bd), "r"(IDESC), "r"(0u), "r"(en) : "memory");
}

// SW128 blocked-atom loader (tcgen05 path)
__device__ __forceinline__ void load_tile_sw(const __nv_bfloat16* __restrict__ G, int rowbase,
                                             int rows_total, char* st, int tid) {
    for (int q = tid; q < 128*16; q += 256) {
        int row = q >> 4, c = q & 15;
        uint4 v = make_uint4(0u,0u,0u,0u);
        int gr = rowbase + row;
        if (gr < rows_total) v = *(const uint4*)(G + (size_t)gr*KDIM + c*8);
        uint32_t b = (uint32_t)(((row>>3) + ((c>>3)<<4))*1024 + (row&7)*128 + (c&7)*16);
        b ^= (b>>3) & 0x70u;
        *(uint4*)(st + b) = v;
    }
}
#endif // USE_TCGEN05

// ---------------- prep: Whh transpose, bias sums, weight bf16 splits ----------------
__global__ void prep_kernel(const float* __restrict__ w_hh,
                            const float* __restrict__ b_ih,
                            const float* __restrict__ b_hh,
                            const float* __restrict__ w_ih,
                            const float* __restrict__ w_fc1,
                            const float* __restrict__ w_fc2) {
    int idx = blockIdx.x*blockDim.x + threadIdx.x;
    int stride = gridDim.x*blockDim.x;
    const int tot = NL*(HID/4)*GATE;
    for (int q = idx; q < tot; q += stride) {
        int j  = q % GATE;
        int k4 = (q / GATE) % (HID/4);
        int l  = q / (GATE*(HID/4));
        const float* wr = w_hh + ((size_t)(l*GATE + j))*HID + k4*4;
        g_Wt4[q] = make_float4(wr[0], wr[1], wr[2], wr[3]);
    }
    for (int q = idx; q < NL*GATE; q += stride) {
        g_blstm[q] = b_ih[q] + b_hh[q];
        g_zero[q]  = 0.f;
    }
    for (int q = idx; q < NL*GATE*EMB; q += stride) split2(w_ih[q],  g_wihh[q], g_wihl[q]);
    for (int q = idx; q < EMB*HID;     q += stride) split2(w_fc1[q], g_wf1h[q], g_wf1l[q]);
    for (int q = idx; q < SEQ*EMB;     q += stride) split2(w_fc2[q], g_wf2h[q], g_wf2l[q]);
}

// ---------------- embed: e = leaky(x @ w_emb^T + b) -> bf16 split, remapped [t][b][e] ----
__global__ __launch_bounds__(256) void embed_kernel(
    const float* __restrict__ A, const float* __restrict__ B,
    const float* __restrict__ bias,
    __nv_bfloat16* __restrict__ outh, __nv_bfloat16* __restrict__ outl)
{
    const int K = FIN, K4 = FIN/4, N = EMB;
    extern __shared__ float4 sm4[];
    float4* As4 = sm4;
    float4* Bs4 = sm4 + 128*K4;

    const int m0 = blockIdx.y * 128;
    const int tid = threadIdx.x;

    for (int q = tid; q < 128*K4; q += 256) {
        int row = q / K4, k4 = q % K4;
        As4[row*K4 + (k4 ^ ((row>>3)&7))] = *(const float4*)(A + ((size_t)(m0+row))*K + (k4<<2));
    }
    for (int q = tid; q < 128*K4; q += 256) {
        int row = q / K4, k4 = q % K4;
        Bs4[row*K4 + (k4 ^ ((row>>3)&7))] = *(const float4*)(B + ((size_t)row)*K + (k4<<2));
    }
    __syncthreads();

    const int tx = tid & 15, ty = tid >> 4;
    const int swa = ty & 7, swb = tx & 7;

    unsigned long long acc[8][8];
    #pragma unroll
    for (int i = 0; i < 8; i++)
        #pragma unroll
        for (int j = 0; j < 8; j++) acc[i][j] = 0ULL;

    for (int k4 = 0; k4 < K4; k4++) {
        int ka = (k4 ^ swa) & (K4-1), kb = (k4 ^ swb) & (K4-1);
        f4u av[8];
        #pragma unroll
        for (int ii = 0; ii < 8; ii++) av[ii].f4 = As4[(ty*8+ii)*K4 + ka];
        #pragma unroll
        for (int jj = 0; jj < 8; jj++) {
            f4u bv; bv.f4 = Bs4[(tx*8+jj)*K4 + kb];
            #pragma unroll
            for (int ii = 0; ii < 8; ii++) {
                ffma2(acc[ii][jj], av[ii].u[0], bv.u[0]);
                ffma2(acc[ii][jj], av[ii].u[1], bv.u[1]);
            }
        }
    }

    #pragma unroll
    for (int ii = 0; ii < 8; ii++) {
        int m = m0 + ty*8 + ii;
        int b = m / SEQ, t = m - b*SEQ;
        size_t orow = (size_t)t*BATCH + b;
        #pragma unroll
        for (int jj = 0; jj < 8; jj++) {
            int n = tx*8 + jj;
            float v = hadd2(acc[ii][jj]) + bias[n];
            v = (v >= 0.f) ? v : 0.01f*v;
            __nv_bfloat16 h, l; split2(v, h, l);
            outh[orow*N + n] = h;
            outl[orow*N + n] = l;
        }
    }
}

// ---------------- tensor GEMM: C = act(A @ B^T + bias), bf16x3 split, fp32 acc --------
// 128x128 tile per CTA, K=128.
//  - sm_103a pass: tcgen05 kind::f16 SS MMA (SW128 blocked-atom tiles).
//  - generic pass: wmma 16x16x16 bf16 (legacy HMMA fallback).
__global__ __launch_bounds__(256) void tgemm_kernel(
    const __nv_bfloat16* __restrict__ Ah, const __nv_bfloat16* __restrict__ Al,
    const __nv_bfloat16* __restrict__ Bh, const __nv_bfloat16* __restrict__ Bl,
    const float* __restrict__ bias, float* __restrict__ C,
    __nv_bfloat16* __restrict__ Ch, __nv_bfloat16* __restrict__ Cl,
    int Ntot, int ldC, int Brows, int act)
{
#if USE_TCGEN05
    extern __shared__ __align__(1024) char smem[];
    __shared__ float s_stage[128][33];
    __shared__ uint32_t s_tmem[1];
    __shared__ __align__(8) unsigned long long s_mbar;

    const int tid = threadIdx.x;
    const int wid = tid >> 5, lane = tid & 31;
    const int m0 = blockIdx.y * 128;
    const int n0 = blockIdx.x * 128;

    char* tAh = smem;
    char* tAl = smem + 32768;
    char* tBh = smem + 65536;
    char* tBl = smem + 98304;

    const uint32_t tptr = smem_u32(s_tmem);
    const uint32_t mbar = smem_u32(&s_mbar);

    if (wid == 0) { TC_ALLOC(tptr, 128); TC_RELINQ(); }
    if (tid == 0) MBAR_INIT(mbar, 1);

    load_tile_sw(Ah, m0, 0x40000000, tAh, tid);
    load_tile_sw(Al, m0, 0x40000000, tAl, tid);
    load_tile_sw(Bh, n0, Brows,      tBh, tid);
    load_tile_sw(Bl, n0, Brows,      tBl, tid);
    __syncthreads();
    FENCE_ASYNC();

    const uint32_t tmem = s_tmem[0];

    if (tid == 0) {
        const uint64_t dAh = mk_desc(smem_u32(tAh));
        const uint64_t dAl = mk_desc(smem_u32(tAl));
        const uint64_t dBh = mk_desc(smem_u32(tBh));
        const uint64_t dBl = mk_desc(smem_u32(tBl));
        const uint32_t offs[8] = {0,2,4,6,1024,1026,1028,1030};
        uint32_t en = 0;
        #pragma unroll
        for (int s = 0; s < 8; s++) { mma_f16_ss(tmem, dAh+offs[s], dBh+offs[s], en); en = 1; }
        #pragma unroll
        for (int s = 0; s < 8; s++) mma_f16_ss(tmem, dAh+offs[s], dBl+offs[s], 1);
        #pragma unroll
        for (int s = 0; s < 8; s++) mma_f16_ss(tmem, dAl+offs[s], dBh+offs[s], 1);
        TC_COMMIT(mbar);
    }
    MBAR_WAIT(mbar, 0);
    TC_FENCE_AFTER();

    const int fullN = (n0 + 128 <= Ntot);
    for (int chunk = 0; chunk < 4; chunk++) {
        if (wid < 4) {
            uint32_t d[32];
            TC_LD_X32(d, tmem + chunk*32);
            TC_WAIT_LD();
            int r = wid*32 + lane;
            #pragma unroll
            for (int c = 0; c < 32; c++) {
                int n = n0 + chunk*32 + c;
                float v = __uint_as_float(d[c]) + ((n < Ntot) ? bias[n] : 0.f);
                if (act) v = (v >= 0.f) ? v : 0.01f*v;
                s_stage[r][c] = v;
            }
        }
        __syncthreads();
        {
            int row = tid >> 1, seg = tid & 1;
            size_t orow = (size_t)(m0 + row);
            if (C) {
                if (fullN) {
                    #pragma unroll
                    for (int i = 0; i < 4; i++) {
                        float4 v = make_float4(s_stage[row][seg*16+i*4+0],
                                               s_stage[row][seg*16+i*4+1],
                                               s_stage[row][seg*16+i*4+2],
                                               s_stage[row][seg*16+i*4+3]);
                        *(float4*)(C + orow*ldC + n0 + chunk*32 + seg*16 + i*4) = v;
                    }
                } else {
                    for (int i = 0; i < 16; i++) {
                        int n = n0 + chunk*32 + seg*16 + i;
                        if (n < Ntot) C[orow*ldC + n] = s_stage[row][seg*16+i];
                    }
                }
            } else {
                #pragma unroll
                for (int i = 0; i < 16; i++) {
                    int n = n0 + chunk*32 + seg*16 + i;
                    float v = s_stage[row][seg*16+i];
                    __nv_bfloat16 h, l; split2(v, h, l);
                    Ch[orow*ldC + n] = h;
                    Cl[orow*ldC + n] = l;
                }
            }
        }
        __syncthreads();
    }
    if (wid == 0) TC_DEALLOC(tmem, 128);

#else  // ---------------- wmma / HMMA fallback ----------------
    using namespace nvcuda;
    const int LDT = 136;  // padded row of bf16 tile (272B: 16B multiple, conflict-stagger)
    extern __shared__ __align__(32) char smem[];
    __nv_bfloat16* sAh = (__nv_bfloat16*)smem;
    __nv_bfloat16* sAl = sAh + 128*LDT;
    __nv_bfloat16* sBh = sAl + 128*LDT;
    __nv_bfloat16* sBl = sBh + 128*LDT;

    const int tid = threadIdx.x;
    const int w = tid >> 5, lane = tid & 31;
    const int m0 = blockIdx.y * 128;
    const int n0 = blockIdx.x * 128;

    for (int q = tid; q < 128*16; q += 256) {
        int row = q >> 4, c = q & 15;
        uint4 va  = *(const uint4*)(Ah + (size_t)(m0+row)*KDIM + c*8);
        uint4 val = *(const uint4*)(Al + (size_t)(m0+row)*KDIM + c*8);
        uint4 vb  = make_uint4(0u,0u,0u,0u), vbl = make_uint4(0u,0u,0u,0u);
        if (n0 + row < Brows) {
            vb  = *(const uint4*)(Bh + (size_t)(n0+row)*KDIM + c*8);
            vbl = *(const uint4*)(Bl + (size_t)(n0+row)*KDIM + c*8);
        }
        *(uint4*)(sAh + row*LDT + c*8) = va;
        *(uint4*)(sAl + row*LDT + c*8) = val;
        *(uint4*)(sBh + row*LDT + c*8) = vb;
        *(uint4*)(sBl + row*LDT + c*8) = vbl;
    }
    __syncthreads();

    wmma::fragment<wmma::accumulator, 16, 16, 16, float> acc[8];
    #pragma unroll
    for (int nt = 0; nt < 8; nt++) wmma::fill_fragment(acc[nt], 0.0f);

    #pragma unroll 1
    for (int ks = 0; ks < 8; ks++) {
        wmma::fragment<wmma::matrix_a, 16, 16, 16, __nv_bfloat16, wmma::row_major> ah, al;
        wmma::load_matrix_sync(ah, sAh + w*16*LDT + ks*16, LDT);
        wmma::load_matrix_sync(al, sAl + w*16*LDT + ks*16, LDT);
        #pragma unroll
        for (int nt = 0; nt < 8; nt++) {
            wmma::fragment<wmma::matrix_b, 16, 16, 16, __nv_bfloat16, wmma::col_major> bh, bl;
            wmma::load_matrix_sync(bh, sBh + nt*16*LDT + ks*16, LDT);
            wmma::load_matrix_sync(bl, sBl + nt*16*LDT + ks*16, LDT);
            wmma::mma_sync(acc[nt], ah, bh, acc[nt]);
            wmma::mma_sync(acc[nt], ah, bl, acc[nt]);
            wmma::mma_sync(acc[nt], al, bh, acc[nt]);
        }
    }
    __syncthreads();   // tiles dead; reuse smem front as per-warp stage

    float* stg = (float*)smem + w*16*20;   // 16 rows, ld 20
    const int r = lane >> 1, seg = lane & 1;
    #pragma unroll 1
    for (int nt = 0; nt < 8; nt++) {
        wmma::store_matrix_sync(stg, acc[nt], 20, wmma::mem_row_major);
        __syncwarp();
        size_t orow = (size_t)(m0 + w*16 + r);
        int nbase = n0 + nt*16 + seg*8;
        float v[8];
        #pragma unroll
        for (int i = 0; i < 8; i++) {
            int n = nbase + i;
            float t = stg[r*20 + seg*8 + i] + ((n < Ntot) ? bias[n] : 0.f);
            if (act) t = (t >= 0.f) ? t : 0.01f*t;
            v[i] = t;
        }
        if (C) {
            if (nbase + 8 <= Ntot) {
                *(float4*)(C + orow*ldC + nbase)     = make_float4(v[0],v[1],v[2],v[3]);
                *(float4*)(C + orow*ldC + nbase + 4) = make_float4(v[4],v[5],v[6],v[7]);
            } else {
                for (int i = 0; i < 8; i++)
                    if (nbase + i < Ntot) C[orow*ldC + nbase + i] = v[i];
            }
        } else {
            #pragma unroll
            for (int i = 0; i < 8; i++) {
                __nv_bfloat16 h, l; split2(v[i], h, l);
                Ch[orow*ldC + nbase + i] = h;
                Cl[orow*ldC + nbase + i] = l;
            }
        }
        __syncwarp();
    }
#endif
}

// ---------------- LSTM recurrence: prefetched A, fast activations ----------------
#define KC 20
__global__ __launch_bounds__(512) void lstm_kernel(const float* __restrict__ A,
                                                   __nv_bfloat16* __restrict__ hsh,
                                                   __nv_bfloat16* __restrict__ hsl)
{
    __shared__ float h_s[4][HID];
    __shared__ float c_s[4][HID];
    __shared__ float g_s[4][GATE];
    extern __shared__ float4 Wc[];

    const int j  = threadIdx.x;
    const int bb = blockIdx.x * 4;
    const int ub = j >> 7, uh = j & 127;

    h_s[ub][uh] = 0.f;
    c_s[ub][uh] = 0.f;

    for (int l = 0; l < NL; l++) {
        const float4* W = g_Wt4 + l*(HID/4)*GATE;
        const float bias = g_blstm[l*GATE + j];
        __syncthreads();
        for (int q = j; q < KC*GATE; q += 512) Wc[q] = W[q];
        f4u wr[32-KC];
        #pragma unroll
        for (int r = 0; r < 32-KC; r++) wr[r].f4 = W[(KC+r)*GATE + j];
        __syncthreads();

        // preload A for t=0
        const float* Ar0 = A + ((size_t)bb)*(NL*GATE) + l*GATE + j;
        float a0 = Ar0[0], a1 = Ar0[NL*GATE], a2 = Ar0[2*NL*GATE], a3 = Ar0[3*NL*GATE];

        for (int t = 0; t < SEQ; t++) {
            // prefetch A for t+1 (latency hidden behind dot compute)
            float na0 = 0.f, na1 = 0.f, na2 = 0.f, na3 = 0.f;
            if (t + 1 < SEQ) {
                const float* Arn = A + ((size_t)((t+1)*BATCH + bb))*(NL*GATE) + l*GATE + j;
                na0 = Arn[0];
                na1 = Arn[NL*GATE];
                na2 = Arn[2*NL*GATE];
                na3 = Arn[3*NL*GATE];
            }

            unsigned long long s0=0ULL, s1=0ULL, s2=0ULL, s3=0ULL;
            #pragma unroll
            for (int k4 = 0; k4 < KC; k4++) {
                f4u wv; wv.f4 = Wc[k4*GATE + j];
                f4u h0; h0.f4 = *(const float4*)&h_s[0][k4<<2];
                f4u h1; h1.f4 = *(const float4*)&h_s[1][k4<<2];
                f4u h2; h2.f4 = *(const float4*)&h_s[2][k4<<2];
                f4u h3; h3.f4 = *(const float4*)&h_s[3][k4<<2];
                ffma2(s0, wv.u[0], h0.u[0]); ffma2(s0, wv.u[1], h0.u[1]);
                ffma2(s1, wv.u[0], h1.u[0]); ffma2(s1, wv.u[1], h1.u[1]);
                ffma2(s2, wv.u[0], h2.u[0]); ffma2(s2, wv.u[1], h2.u[1]);
                ffma2(s3, wv.u[0], h3.u[0]); ffma2(s3, wv.u[1], h3.u[1]);
            }
            #pragma unroll
            for (int r = 0; r < 32-KC; r++) {
                int k4 = KC + r;
                f4u h0; h0.f4 = *(const float4*)&h_s[0][k4<<2];
                f4u h1; h1.f4 = *(const float4*)&h_s[1][k4<<2];
                f4u h2; h2.f4 = *(const float4*)&h_s[2][k4<<2];
                f4u h3; h3.f4 = *(const float4*)&h_s[3][k4<<2];
                ffma2(s0, wr[r].u[0], h0.u[0]); ffma2(s0, wr[r].u[1], h0.u[1]);
                ffma2(s1, wr[r].u[0], h1.u[0]); ffma2(s1, wr[r].u[1], h1.u[1]);
                ffma2(s2, wr[r].u[0], h2.u[0]); ffma2(s2, wr[r].u[1], h2.u[1]);
                ffma2(s3, wr[r].u[0], h3.u[0]); ffma2(s3, wr[r].u[1], h3.u[1]);
            }
            g_s[0][j] = hadd2(s0) + a0 + bias;
            g_s[1][j] = hadd2(s1) + a1 + bias;
            g_s[2][j] = hadd2(s2) + a2 + bias;
            g_s[3][j] = hadd2(s3) + a3 + bias;
            __syncthreads();

            {
                float ig = g_s[ub][uh];
                float fg = g_s[ub][HID   + uh];
                float gg = g_s[ub][2*HID + uh];
                float og = g_s[ub][3*HID + uh];
                float cc = fsig(fg)*c_s[ub][uh] + fsig(ig)*ftanh(gg);
                float hh = fsig(og)*ftanh(cc);
                c_s[ub][uh] = cc;
                h_s[ub][uh] = hh;
                if (l == NL-1) {
                    __nv_bfloat16 hb, lb; split2(hh, hb, lb);
                    size_t idx = ((size_t)(bb+ub)*SEQ + t)*HID + uh;
                    hsh[idx] = hb;
                    hsl[idx] = lb;
                }
            }
            __syncthreads();
            a0 = na0; a1 = na1; a2 = na2; a3 = na3;
        }
    }
}

// ---------------- fused sinkhorn ----------------
__global__ __launch_bounds__(256) void sinkhorn_kernel(const float* __restrict__ Min,
                                                       float* __restrict__ out)
{
    extern __shared__ float Ms[];
    const int b = blockIdx.x, tid = threadIdx.x;
    const float4* src = (const float4*)(Min + (size_t)b*SEQ*SEQ);
    float4* dst = (float4*)(out + (size_t)b*SEQ*SEQ);

    for (int q = tid; q < SEQ*SEQ/4; q += 256) {
        float4 v = src[q];
        v.x = __expf(v.x); v.y = __expf(v.y); v.z = __expf(v.z); v.w = __expf(v.w);
        ((float4*)Ms)[q] = v;
    }
    __syncthreads();

    const int lane = tid & 31, w = tid >> 5;
    for (int it = 0; it < 5; it++) {
        for (int r = w; r < SEQ; r += 8) {
            float s = 0.f;
            for (int q = lane; q < SEQ; q += 32) s += Ms[r*SEQ + q];
            #pragma unroll
            for (int off = 16; off; off >>= 1) s += __shfl_xor_sync(0xffffffffu, s, off);
            float inv = 1.0f / s;
            for (int q = lane; q < SEQ; q += 32) Ms[r*SEQ + q] *= inv;
        }
        __syncthreads();
        if (tid < SEQ) {
            float s = 0.f;
            for (int r = 0; r < SEQ; r++) s += Ms[r*SEQ + tid];
            float inv = 1.0f / s;
            for (int r = 0; r < SEQ; r++) Ms[r*SEQ + tid] *= inv;
        }
        __syncthreads();
    }

    for (int q = tid; q < SEQ*SEQ/4; q += 256) dst[q] = ((const float4*)Ms)[q];
}

// ---------------- launch ----------------
extern "C" void kernel_launch(void* const* d_in, const int* in_sizes, int n_in,
                              void* d_out, int out_size)
{
    const float* x     = (const float*)d_in[0];
    const float* w_emb = (const float*)d_in[1];
    const float* b_emb = (const float*)d_in[2];
    const float* w_ih  = (const float*)d_in[3];
    const float* w_hh  = (const float*)d_in[4];
    const float* b_ih  = (const float*)d_in[5];
    const float* b_hh  = (const float*)d_in[6];
    const float* w_fc1 = (const float*)d_in[7];
    const float* b_fc1 = (const float*)d_in[8];
    const float* w_fc2 = (const float*)d_in[9];
    const float* b_fc2 = (const float*)d_in[10];
    float* out = (float*)d_out;

    float *Ab, *Mb, *zero;
    __nv_bfloat16 *xsh,*xsl,*wihh,*wihl,*wf1h,*wf1l,*wf2h,*wf2l,*hsh,*hsl,*f1h,*f1l;
    cudaGetSymbolAddress((void**)&Ab,   g_A);
    cudaGetSymbolAddress((void**)&Mb,   g_Mb);
    cudaGetSymbolAddress((void**)&zero, g_zero);
    cudaGetSymbolAddress((void**)&xsh,  g_xsh);  cudaGetSymbolAddress((void**)&xsl, g_xsl);
    cudaGetSymbolAddress((void**)&wihh, g_wihh); cudaGetSymbolAddress((void**)&wihl, g_wihl);
    cudaGetSymbolAddress((void**)&wf1h, g_wf1h); cudaGetSymbolAddress((void**)&wf1l, g_wf1l);
    cudaGetSymbolAddress((void**)&wf2h, g_wf2h); cudaGetSymbolAddress((void**)&wf2l, g_wf2l);
    cudaGetSymbolAddress((void**)&hsh,  g_hsh);  cudaGetSymbolAddress((void**)&hsl, g_hsl);
    cudaGetSymbolAddress((void**)&f1h,  g_f1h);  cudaGetSymbolAddress((void**)&f1l, g_f1l);

    const int TG_SMEM = 4*128*136*2;   // 139264 (covers both paths)
    cudaFuncSetAttribute(tgemm_kernel,    cudaFuncAttributeMaxDynamicSharedMemorySize, TG_SMEM);
    cudaFuncSetAttribute(lstm_kernel,     cudaFuncAttributeMaxDynamicSharedMemorySize, KC*GATE*16);
    cudaFuncSetAttribute(sinkhorn_kernel, cudaFuncAttributeMaxDynamicSharedMemorySize, SEQ*SEQ*4);

    // 1) prep: Whh transpose, bias sum, weight splits
    prep_kernel<<<128, 256>>>(w_hh, b_ih, b_hh, w_ih, w_fc1, w_fc2);
    // 2) embed -> xs bf16 split, [t][b][e]
    embed_kernel<<<dim3(1, MROWS/128), 256, 2*128*(FIN/4)*16>>>(x, w_emb, b_emb, xsh, xsl);
    // 3) gemm3 (tensor): A = xs @ Wih^T  (LSTM bias added in lstm kernel)
    tgemm_kernel<<<dim3(NL*GATE/128, MROWS/128), 256, TG_SMEM>>>(
        xsh, xsl, wihh, wihl, zero, Ab, nullptr, nullptr, NL*GATE, NL*GATE, NL*GATE, 0);
    // 4) LSTM recurrence -> hs bf16 split
    lstm_kernel<<<BATCH/4, 512, KC*GATE*16>>>(Ab, hsh, hsl);
    // 5) fc1 (tensor, leaky) -> f1 bf16 split
    tgemm_kernel<<<dim3(1, MROWS/128), 256, TG_SMEM>>>(
        hsh, hsl, wf1h, wf1l, b_fc1, nullptr, f1h, f1l, EMB, EMB, EMB, 1);
    // 6) fc2 (tensor) -> M fp32
    tgemm_kernel<<<dim3(2, MROWS/128), 256, TG_SMEM>>>(
        f1h, f1l, wf2h, wf2l, b_fc2, Mb, nullptr, nullptr, SEQ, SEQ, SEQ, 0);
    // 7) sinkhorn
    sinkhorn_kernel<<<BATCH, 256, SEQ*SEQ*4>>>(Mb, out);
}

// round 6
// speedup vs baseline: 1.8225x; 1.3536x over previous
#include <cuda_runtime.h>
#include <cuda_bf16.h>
#include <mma.h>
#include <math.h>
#include <stdint.h>

#define BATCH 512
#define SEQ   200
#define FIN   32
#define EMB   128
#define HID   128
#define GATE  512            // 4*HID
#define NL    2
#define MROWS (BATCH*SEQ)    // 102400
#define KDIM  128

// ---------------- scratch (__device__ globals) ----------------
__device__ float  g_A [(size_t)MROWS*NL*GATE];          // LSTM input projections (fp32)
__device__ float  g_Mb[(size_t)MROWS*SEQ];              // fc2 out [b][n][n']
__device__ float4 g_Wt4[NL*(HID/4)*GATE];               // Whh transposed k-major
__device__ float  g_blstm[NL*GATE];                     // b_ih + b_hh
__device__ float  g_zero[NL*GATE];                      // zero bias for gemm3

// bf16 hi/lo split operands for tensor GEMMs
__device__ __nv_bfloat16 g_xsh[(size_t)MROWS*EMB], g_xsl[(size_t)MROWS*EMB];
__device__ __nv_bfloat16 g_wihh[NL*GATE*EMB],      g_wihl[NL*GATE*EMB];
__device__ __nv_bfloat16 g_wf1h[EMB*HID],          g_wf1l[EMB*HID];
__device__ __nv_bfloat16 g_wf2h[SEQ*EMB],          g_wf2l[SEQ*EMB];
__device__ __nv_bfloat16 g_hsh[(size_t)MROWS*HID], g_hsl[(size_t)MROWS*HID];
__device__ __nv_bfloat16 g_f1h[(size_t)MROWS*EMB], g_f1l[(size_t)MROWS*EMB];

__device__ __forceinline__ void split2(float v, __nv_bfloat16& h, __nv_bfloat16& l) {
    h = __float2bfloat16(v);
    l = __float2bfloat16(v - __bfloat162float(h));
}
__device__ __forceinline__ unsigned short bf_bits(__nv_bfloat16 b) {
    union { __nv_bfloat16 b; unsigned short u; } c; c.b = b; return c.u;
}

// packed fp32x2 FMA (embed + lstm scalar paths)
union f4u { float4 f4; unsigned long long u[2]; };
__device__ __forceinline__ void ffma2(unsigned long long& d,
                                      unsigned long long a,
                                      unsigned long long b) {
    asm("fma.rn.f32x2 %0, %1, %2, %0;" : "+l"(d) : "l"(a), "l"(b));
}
__device__ __forceinline__ float hadd2(unsigned long long v) {
    union { unsigned long long u; float2 f; } c; c.u = v;
    return c.f.x + c.f.y;
}

// fast activations (MUFU-based)
__device__ __forceinline__ float fsig(float x)  { return __fdividef(1.f, 1.f + __expf(-x)); }
__device__ __forceinline__ float ftanh(float x) { return __fdividef(2.f, 1.f + __expf(-2.f*x)) - 1.f; }

// ---------------- prep: Whh transpose, bias sums, weight bf16 splits ----------------
__global__ void prep_kernel(const float* __restrict__ w_hh,
                            const float* __restrict__ b_ih,
                            const float* __restrict__ b_hh,
                            const float* __restrict__ w_ih,
                            const float* __restrict__ w_fc1,
                            const float* __restrict__ w_fc2) {
    int idx = blockIdx.x*blockDim.x + threadIdx.x;
    int stride = gridDim.x*blockDim.x;
    const int tot = NL*(HID/4)*GATE;
    for (int q = idx; q < tot; q += stride) {
        int j  = q % GATE;
        int k4 = (q / GATE) % (HID/4);
        int l  = q / (GATE*(HID/4));
        const float* wr = w_hh + ((size_t)(l*GATE + j))*HID + k4*4;
        g_Wt4[q] = make_float4(wr[0], wr[1], wr[2], wr[3]);
    }
    for (int q = idx; q < NL*GATE; q += stride) {
        g_blstm[q] = b_ih[q] + b_hh[q];
        g_zero[q]  = 0.f;
    }
    for (int q = idx; q < NL*GATE*EMB; q += stride) split2(w_ih[q],  g_wihh[q], g_wihl[q]);
    for (int q = idx; q < EMB*HID;     q += stride) split2(w_fc1[q], g_wf1h[q], g_wf1l[q]);
    for (int q = idx; q < SEQ*EMB;     q += stride) split2(w_fc2[q], g_wf2h[q], g_wf2l[q]);
}

// ---------------- embed: e = leaky(x @ w_emb^T + b) -> bf16 split, remapped [t][b][e] ----
__global__ __launch_bounds__(256) void embed_kernel(
    const float* __restrict__ A, const float* __restrict__ B,
    const float* __restrict__ bias,
    __nv_bfloat16* __restrict__ outh, __nv_bfloat16* __restrict__ outl)
{
    const int K = FIN, K4 = FIN/4, N = EMB;
    extern __shared__ float4 sm4[];
    float4* As4 = sm4;
    float4* Bs4 = sm4 + 128*K4;

    const int m0 = blockIdx.y * 128;
    const int tid = threadIdx.x;

    for (int q = tid; q < 128*K4; q += 256) {
        int row = q / K4, k4 = q % K4;
        As4[row*K4 + (k4 ^ ((row>>3)&7))] = *(const float4*)(A + ((size_t)(m0+row))*K + (k4<<2));
    }
    for (int q = tid; q < 128*K4; q += 256) {
        int row = q / K4, k4 = q % K4;
        Bs4[row*K4 + (k4 ^ ((row>>3)&7))] = *(const float4*)(B + ((size_t)row)*K + (k4<<2));
    }
    __syncthreads();

    const int tx = tid & 15, ty = tid >> 4;
    const int swa = ty & 7, swb = tx & 7;

    unsigned long long acc[8][8];
    #pragma unroll
    for (int i = 0; i < 8; i++)
        #pragma unroll
        for (int j = 0; j < 8; j++) acc[i][j] = 0ULL;

    for (int k4 = 0; k4 < K4; k4++) {
        int ka = (k4 ^ swa) & (K4-1), kb = (k4 ^ swb) & (K4-1);
        f4u av[8];
        #pragma unroll
        for (int ii = 0; ii < 8; ii++) av[ii].f4 = As4[(ty*8+ii)*K4 + ka];
        #pragma unroll
        for (int jj = 0; jj < 8; jj++) {
            f4u bv; bv.f4 = Bs4[(tx*8+jj)*K4 + kb];
            #pragma unroll
            for (int ii = 0; ii < 8; ii++) {
                ffma2(acc[ii][jj], av[ii].u[0], bv.u[0]);
                ffma2(acc[ii][jj], av[ii].u[1], bv.u[1]);
            }
        }
    }

    #pragma unroll
    for (int ii = 0; ii < 8; ii++) {
        int m = m0 + ty*8 + ii;
        int b = m / SEQ, t = m - b*SEQ;
        size_t orow = (size_t)t*BATCH + b;
        union { unsigned short s[8]; uint4 v; } ph, pl;
        #pragma unroll
        for (int jj = 0; jj < 8; jj++) {
            int n = tx*8 + jj;
            float v = hadd2(acc[ii][jj]) + bias[n];
            v = (v >= 0.f) ? v : 0.01f*v;
            __nv_bfloat16 h, l; split2(v, h, l);
            ph.s[jj] = bf_bits(h);
            pl.s[jj] = bf_bits(l);
        }
        *(uint4*)(outh + orow*N + tx*8) = ph.v;
        *(uint4*)(outl + orow*N + tx*8) = pl.v;
    }
}

// ---------------- tensor GEMM: C = act(A @ B^T + bias), bf16x3 split, fp32 acc --------
// wmma 16x16x16 bf16 (legacy HMMA path; compiles on generic sm_103).
__global__ __launch_bounds__(256) void tgemm_kernel(
    const __nv_bfloat16* __restrict__ Ah, const __nv_bfloat16* __restrict__ Al,
    const __nv_bfloat16* __restrict__ Bh, const __nv_bfloat16* __restrict__ Bl,
    const float* __restrict__ bias, float* __restrict__ C,
    __nv_bfloat16* __restrict__ Ch, __nv_bfloat16* __restrict__ Cl,
    int Ntot, int ldC, int Brows, int act)
{
    using namespace nvcuda;
    const int LDT = 136;  // padded bf16 row
    extern __shared__ __align__(32) char smem[];
    __nv_bfloat16* sAh = (__nv_bfloat16*)smem;
    __nv_bfloat16* sAl = sAh + 128*LDT;
    __nv_bfloat16* sBh = sAl + 128*LDT;
    __nv_bfloat16* sBl = sBh + 128*LDT;

    const int tid = threadIdx.x;
    const int w = tid >> 5, lane = tid & 31;
    const int m0 = blockIdx.y * 128;
    const int n0 = blockIdx.x * 128;

    for (int q = tid; q < 128*16; q += 256) {
        int row = q >> 4, c = q & 15;
        uint4 va  = *(const uint4*)(Ah + (size_t)(m0+row)*KDIM + c*8);
        uint4 val = *(const uint4*)(Al + (size_t)(m0+row)*KDIM + c*8);
        uint4 vb  = make_uint4(0u,0u,0u,0u), vbl = make_uint4(0u,0u,0u,0u);
        if (n0 + row < Brows) {
            vb  = *(const uint4*)(Bh + (size_t)(n0+row)*KDIM + c*8);
            vbl = *(const uint4*)(Bl + (size_t)(n0+row)*KDIM + c*8);
        }
        *(uint4*)(sAh + row*LDT + c*8) = va;
        *(uint4*)(sAl + row*LDT + c*8) = val;
        *(uint4*)(sBh + row*LDT + c*8) = vb;
        *(uint4*)(sBl + row*LDT + c*8) = vbl;
    }
    __syncthreads();

    wmma::fragment<wmma::accumulator, 16, 16, 16, float> acc[8];
    #pragma unroll
    for (int nt = 0; nt < 8; nt++) wmma::fill_fragment(acc[nt], 0.0f);

    #pragma unroll 2
    for (int ks = 0; ks < 8; ks++) {
        wmma::fragment<wmma::matrix_a, 16, 16, 16, __nv_bfloat16, wmma::row_major> ah, al;
        wmma::load_matrix_sync(ah, sAh + w*16*LDT + ks*16, LDT);
        wmma::load_matrix_sync(al, sAl + w*16*LDT + ks*16, LDT);
        #pragma unroll
        for (int nt = 0; nt < 8; nt++) {
            wmma::fragment<wmma::matrix_b, 16, 16, 16, __nv_bfloat16, wmma::col_major> bh, bl;
            wmma::load_matrix_sync(bh, sBh + nt*16*LDT + ks*16, LDT);
            wmma::load_matrix_sync(bl, sBl + nt*16*LDT + ks*16, LDT);
            wmma::mma_sync(acc[nt], ah, bh, acc[nt]);
            wmma::mma_sync(acc[nt], ah, bl, acc[nt]);
            wmma::mma_sync(acc[nt], al, bh, acc[nt]);
        }
    }
    __syncthreads();   // tiles dead; reuse smem front as per-warp stage

    float* stg = (float*)smem + w*16*20;   // 16 rows, ld 20
    const int r = lane >> 1, seg = lane & 1;
    #pragma unroll 1
    for (int nt = 0; nt < 8; nt++) {
        wmma::store_matrix_sync(stg, acc[nt], 20, wmma::mem_row_major);
        __syncwarp();
        size_t orow = (size_t)(m0 + w*16 + r);
        int nbase = n0 + nt*16 + seg*8;
        float v[8];
        #pragma unroll
        for (int i = 0; i < 8; i++) {
            int n = nbase + i;
            float t = stg[r*20 + seg*8 + i] + ((n < Ntot) ? bias[n] : 0.f);
            if (act) t = (t >= 0.f) ? t : 0.01f*t;
            v[i] = t;
        }
        if (C) {
            if (nbase + 8 <= Ntot) {
                *(float4*)(C + orow*ldC + nbase)     = make_float4(v[0],v[1],v[2],v[3]);
                *(float4*)(C + orow*ldC + nbase + 4) = make_float4(v[4],v[5],v[6],v[7]);
            } else {
                for (int i = 0; i < 8; i++)
                    if (nbase + i < Ntot) C[orow*ldC + nbase + i] = v[i];
            }
        } else {
            union { unsigned short s[8]; uint4 q; } ph, pl;
            #pragma unroll
            for (int i = 0; i < 8; i++) {
                __nv_bfloat16 h, l; split2(v[i], h, l);
                ph.s[i] = bf_bits(h);
                pl.s[i] = bf_bits(l);
            }
            *(uint4*)(Ch + orow*ldC + nbase) = ph.q;
            *(uint4*)(Cl + orow*ldC + nbase) = pl.q;
        }
        __syncwarp();
    }
}

// ---------------- LSTM recurrence: 256 threads, 2 gates x 4 batches per thread --------
// Crossbar halved vs R5: h-broadcast reused for 2 gates; 16 k4/gate cached in regs.
#define KC 16          // k4 rows of Whh kept in smem (all 512 gates)
#define KR 16          // k4 rows per gate held in registers
__global__ __launch_bounds__(256) void lstm_kernel(const float* __restrict__ A,
                                                   __nv_bfloat16* __restrict__ hsh,
                                                   __nv_bfloat16* __restrict__ hsl)
{
    __shared__ float h_s[4][HID];
    __shared__ float c_s[4][HID];
    __shared__ float g_s[4][GATE];
    extern __shared__ float4 Wc[];   // KC*GATE float4 = 128 KB

    const int tid = threadIdx.x;
    const int j0 = tid, j1 = tid + 256;
    const int bb = blockIdx.x * 4;
    const int ub0 = tid >> 7,      uh = tid & 127;   // update pair 0: batches 0,1
    const int ub1 = 2 + (tid >> 7);                  // update pair 1: batches 2,3

    h_s[ub0][uh] = 0.f; h_s[ub1][uh] = 0.f;
    c_s[ub0][uh] = 0.f; c_s[ub1][uh] = 0.f;

    for (int l = 0; l < NL; l++) {
        const float4* W = g_Wt4 + l*(HID/4)*GATE;
        const float bias0 = g_blstm[l*GATE + j0];
        const float bias1 = g_blstm[l*GATE + j1];
        __syncthreads();
        for (int q = tid; q < KC*GATE; q += 256) Wc[q] = W[q];
        f4u w0[KR], w1[KR];
        #pragma unroll
        for (int r = 0; r < KR; r++) {
            w0[r].f4 = W[(KC+r)*GATE + j0];
            w1[r].f4 = W[(KC+r)*GATE + j1];
        }
        __syncthreads();

        // preload A for t=0
        float a0[4], a1[4];
        {
            const float* Ar = A + (size_t)bb*(NL*GATE) + l*GATE;
            #pragma unroll
            for (int b = 0; b < 4; b++) {
                a0[b] = Ar[(size_t)b*(NL*GATE) + j0];
                a1[b] = Ar[(size_t)b*(NL*GATE) + j1];
            }
        }

        for (int t = 0; t < SEQ; t++) {
            float na0[4], na1[4];
            if (t + 1 < SEQ) {
                const float* Arn = A + ((size_t)((t+1)*BATCH + bb))*(NL*GATE) + l*GATE;
                #pragma unroll
                for (int b = 0; b < 4; b++) {
                    na0[b] = Arn[(size_t)b*(NL*GATE) + j0];
                    na1[b] = Arn[(size_t)b*(NL*GATE) + j1];
                }
            } else {
                #pragma unroll
                for (int b = 0; b < 4; b++) { na0[b] = 0.f; na1[b] = 0.f; }
            }

            unsigned long long s0[4] = {0,0,0,0}, s1[4] = {0,0,0,0};
            #pragma unroll
            for (int k4 = 0; k4 < KC; k4++) {
                f4u wv0; wv0.f4 = Wc[k4*GATE + j0];
                f4u wv1; wv1.f4 = Wc[k4*GATE + j1];
                #pragma unroll
                for (int b = 0; b < 4; b++) {
                    f4u hb; hb.f4 = *(const float4*)&h_s[b][k4<<2];
                    ffma2(s0[b], wv0.u[0], hb.u[0]); ffma2(s0[b], wv0.u[1], hb.u[1]);
                    ffma2(s1[b], wv1.u[0], hb.u[0]); ffma2(s1[b], wv1.u[1], hb.u[1]);
                }
            }
            #pragma unroll
            for (int r = 0; r < KR; r++) {
                int k4 = KC + r;
                #pragma unroll
                for (int b = 0; b < 4; b++) {
                    f4u hb; hb.f4 = *(const float4*)&h_s[b][k4<<2];
                    ffma2(s0[b], w0[r].u[0], hb.u[0]); ffma2(s0[b], w0[r].u[1], hb.u[1]);
                    ffma2(s1[b], w1[r].u[0], hb.u[0]); ffma2(s1[b], w1[r].u[1], hb.u[1]);
                }
            }
            #pragma unroll
            for (int b = 0; b < 4; b++) {
                g_s[b][j0] = hadd2(s0[b]) + a0[b] + bias0;
                g_s[b][j1] = hadd2(s1[b]) + a1[b] + bias1;
            }
            __syncthreads();

            // pointwise update: 2 (batch, hid) pairs per thread
            #pragma unroll
            for (int p = 0; p < 2; p++) {
                int b = p ? ub1 : ub0;
                float ig = g_s[b][uh];
                float fg = g_s[b][HID   + uh];
                float gg = g_s[b][2*HID + uh];
                float og = g_s[b][3*HID + uh];
                float cc = fsig(fg)*c_s[b][uh] + fsig(ig)*ftanh(gg);
                float hh = fsig(og)*ftanh(cc);
                c_s[b][uh] = cc;
                h_s[b][uh] = hh;
                if (l == NL-1) {
                    __nv_bfloat16 hb, lb; split2(hh, hb, lb);
                    size_t idx = ((size_t)(bb+b)*SEQ + t)*HID + uh;
                    hsh[idx] = hb;
                    hsl[idx] = lb;
                }
            }
            __syncthreads();
            #pragma unroll
            for (int b = 0; b < 4; b++) { a0[b] = na0[b]; a1[b] = na1[b]; }
        }
    }
}

// ---------------- fused sinkhorn (512 threads) ----------------
__global__ __launch_bounds__(512) void sinkhorn_kernel(const float* __restrict__ Min,
                                                       float* __restrict__ out)
{
    extern __shared__ float Ms[];
    const int b = blockIdx.x, tid = threadIdx.x;
    const float4* src = (const float4*)(Min + (size_t)b*SEQ*SEQ);
    float4* dst = (float4*)(out + (size_t)b*SEQ*SEQ);

    for (int q = tid; q < SEQ*SEQ/4; q += 512) {
        float4 v = src[q];
        v.x = __expf(v.x); v.y = __expf(v.y); v.z = __expf(v.z); v.w = __expf(v.w);
        ((float4*)Ms)[q] = v;
    }
    __syncthreads();

    const int lane = tid & 31, w = tid >> 5;   // 16 warps
    for (int it = 0; it < 5; it++) {
        for (int r = w; r < SEQ; r += 16) {
            float s = 0.f;
            for (int q = lane; q < SEQ; q += 32) s += Ms[r*SEQ + q];
            #pragma unroll
            for (int off = 16; off; off >>= 1) s += __shfl_xor_sync(0xffffffffu, s, off);
            float inv = 1.0f / s;
            for (int q = lane; q < SEQ; q += 32) Ms[r*SEQ + q] *= inv;
        }
        __syncthreads();
        if (tid < SEQ) {
            float s = 0.f;
            for (int r = 0; r < SEQ; r++) s += Ms[r*SEQ + tid];
            float inv = 1.0f / s;
            for (int r = 0; r < SEQ; r++) Ms[r*SEQ + tid] *= inv;
        }
        __syncthreads();
    }

    for (int q = tid; q < SEQ*SEQ/4; q += 512) dst[q] = ((const float4*)Ms)[q];
}

// ---------------- launch ----------------
extern "C" void kernel_launch(void* const* d_in, const int* in_sizes, int n_in,
                              void* d_out, int out_size)
{
    const float* x     = (const float*)d_in[0];
    const float* w_emb = (const float*)d_in[1];
    const float* b_emb = (const float*)d_in[2];
    const float* w_ih  = (const float*)d_in[3];
    const float* w_hh  = (const float*)d_in[4];
    const float* b_ih  = (const float*)d_in[5];
    const float* b_hh  = (const float*)d_in[6];
    const float* w_fc1 = (const float*)d_in[7];
    const float* b_fc1 = (const float*)d_in[8];
    const float* w_fc2 = (const float*)d_in[9];
    const float* b_fc2 = (const float*)d_in[10];
    float* out = (float*)d_out;

    float *Ab, *Mb, *zero;
    __nv_bfloat16 *xsh,*xsl,*wihh,*wihl,*wf1h,*wf1l,*wf2h,*wf2l,*hsh,*hsl,*f1h,*f1l;
    cudaGetSymbolAddress((void**)&Ab,   g_A);
    cudaGetSymbolAddress((void**)&Mb,   g_Mb);
    cudaGetSymbolAddress((void**)&zero, g_zero);
    cudaGetSymbolAddress((void**)&xsh,  g_xsh);  cudaGetSymbolAddress((void**)&xsl, g_xsl);
    cudaGetSymbolAddress((void**)&wihh, g_wihh); cudaGetSymbolAddress((void**)&wihl, g_wihl);
    cudaGetSymbolAddress((void**)&wf1h, g_wf1h); cudaGetSymbolAddress((void**)&wf1l, g_wf1l);
    cudaGetSymbolAddress((void**)&wf2h, g_wf2h); cudaGetSymbolAddress((void**)&wf2l, g_wf2l);
    cudaGetSymbolAddress((void**)&hsh,  g_hsh);  cudaGetSymbolAddress((void**)&hsl, g_hsl);
    cudaGetSymbolAddress((void**)&f1h,  g_f1h);  cudaGetSymbolAddress((void**)&f1l, g_f1l);

    const int TG_SMEM = 4*128*136*2;   // 139264
    const int LS_SMEM = KC*GATE*16;    // 131072
    cudaFuncSetAttribute(tgemm_kernel,    cudaFuncAttributeMaxDynamicSharedMemorySize, TG_SMEM);
    cudaFuncSetAttribute(lstm_kernel,     cudaFuncAttributeMaxDynamicSharedMemorySize, LS_SMEM);
    cudaFuncSetAttribute(sinkhorn_kernel, cudaFuncAttributeMaxDynamicSharedMemorySize, SEQ*SEQ*4);

    // 1) prep: Whh transpose, bias sum, weight splits
    prep_kernel<<<128, 256>>>(w_hh, b_ih, b_hh, w_ih, w_fc1, w_fc2);
    // 2) embed -> xs bf16 split, [t][b][e]
    embed_kernel<<<dim3(1, MROWS/128), 256, 2*128*(FIN/4)*16>>>(x, w_emb, b_emb, xsh, xsl);
    // 3) gemm3 (tensor): A = xs @ Wih^T  (LSTM bias added in lstm kernel)
    tgemm_kernel<<<dim3(NL*GATE/128, MROWS/128), 256, TG_SMEM>>>(
        xsh, xsl, wihh, wihl, zero, Ab, nullptr, nullptr, NL*GATE, NL*GATE, NL*GATE, 0);
    // 4) LSTM recurrence -> hs bf16 split
    lstm_kernel<<<BATCH/4, 256, LS_SMEM>>>(Ab, hsh, hsl);
    // 5) fc1 (tensor, leaky) -> f1 bf16 split
    tgemm_kernel<<<dim3(1, MROWS/128), 256, TG_SMEM>>>(
        hsh, hsl, wf1h, wf1l, b_fc1, nullptr, f1h, f1l, EMB, EMB, EMB, 1);
    // 6) fc2 (tensor) -> M fp32
    tgemm_kernel<<<dim3(2, MROWS/128), 256, TG_SMEM>>>(
        f1h, f1l, wf2h, wf2l, b_fc2, Mb, nullptr, nullptr, SEQ, SEQ, SEQ, 0);
    // 7) sinkhorn
    sinkhorn_kernel<<<BATCH, 512, SEQ*SEQ*4>>>(Mb, out);
}